// round 4
// baseline (speedup 1.0000x reference)
#include <cuda_runtime.h>
#include <cstdint>

// LIF recurrence: T=64 sequential steps, B*N = 524288 independent lanes.
//   h = v + (x - v) * 0.5 ; s = (h>=1) ; v = s ? 0 : h
// Pure HBM stream: 134 MB in + 134 MB out, zero reuse.
// R4: R1 skeleton (best so far, 36.9us) + streaming cache hints
// (__ldcs/__stcs: evict-first, no L1/L2 pollution for use-once lines)
// + unroll 8 so ptxas front-batches 8 independent LDG.128s per body.

static constexpr int T = 64;

__global__ void __launch_bounds__(256) lif_kernel(const float4* __restrict__ x,
                                                  float4* __restrict__ out,
                                                  int lanes4)  // B*N/4 per timestep
{
    int i = blockIdx.x * blockDim.x + threadIdx.x;
    if (i >= lanes4) return;

    float4 v = make_float4(0.f, 0.f, 0.f, 0.f);

    #pragma unroll 8
    for (int t = 0; t < T; ++t) {
        // streaming load: used once, evict-first
        float4 xt = __ldcs(&x[(size_t)t * lanes4 + i]);

        float4 h, s;
        h.x = v.x + (xt.x - v.x) * 0.5f;
        h.y = v.y + (xt.y - v.y) * 0.5f;
        h.z = v.z + (xt.z - v.z) * 0.5f;
        h.w = v.w + (xt.w - v.w) * 0.5f;

        s.x = (h.x >= 1.0f) ? 1.0f : 0.0f;
        s.y = (h.y >= 1.0f) ? 1.0f : 0.0f;
        s.z = (h.z >= 1.0f) ? 1.0f : 0.0f;
        s.w = (h.w >= 1.0f) ? 1.0f : 0.0f;

        v.x = (h.x >= 1.0f) ? 0.0f : h.x;
        v.y = (h.y >= 1.0f) ? 0.0f : h.y;
        v.z = (h.z >= 1.0f) ? 0.0f : h.z;
        v.w = (h.w >= 1.0f) ? 0.0f : h.w;

        // streaming store: written once, never re-read
        __stcs(&out[(size_t)t * lanes4 + i], s);
    }
}

extern "C" void kernel_launch(void* const* d_in, const int* in_sizes, int n_in,
                              void* d_out, int out_size)
{
    const float4* x = (const float4*)d_in[0];
    float4* out = (float4*)d_out;

    int total = in_sizes[0];          // T * B * N
    int lanes = total / T;            // 524288
    int lanes4 = lanes / 4;           // 131072

    int threads = 256;
    int blocks = (lanes4 + threads - 1) / threads;
    lif_kernel<<<blocks, threads>>>(x, out, lanes4);
}

// round 5
// speedup vs baseline: 1.1766x; 1.1766x over previous
#include <cuda_runtime.h>
#include <cstdint>

// LIF recurrence: T=64 sequential steps, B*N = 524288 independent lanes.
//   h = v + (x - v) * 0.5 ; s = (h>=1) ; v = s ? 0 : h
// Pure HBM stream: 134 MB in + 134 MB out. Best so far: R1 (36.9us, 73% DRAM).
// R5: R1 skeleton, load-ahead distance 2 via SCALAR prefetch regs (no array
// rotation), 2 timesteps per body, unroll 4 -> 8 independent LDG.128 batched
// per SASS body. Plain loads/stores (no .cs — R4 showed ptxas deschedules).

static constexpr int T = 64;

__device__ __forceinline__ void lif_step(float4& v, const float4 xt, float4& s)
{
    float4 h;
    h.x = v.x + (xt.x - v.x) * 0.5f;
    h.y = v.y + (xt.y - v.y) * 0.5f;
    h.z = v.z + (xt.z - v.z) * 0.5f;
    h.w = v.w + (xt.w - v.w) * 0.5f;

    s.x = (h.x >= 1.0f) ? 1.0f : 0.0f;
    s.y = (h.y >= 1.0f) ? 1.0f : 0.0f;
    s.z = (h.z >= 1.0f) ? 1.0f : 0.0f;
    s.w = (h.w >= 1.0f) ? 1.0f : 0.0f;

    v.x = (h.x >= 1.0f) ? 0.0f : h.x;
    v.y = (h.y >= 1.0f) ? 0.0f : h.y;
    v.z = (h.z >= 1.0f) ? 0.0f : h.z;
    v.w = (h.w >= 1.0f) ? 0.0f : h.w;
}

__global__ void __launch_bounds__(256) lif_kernel(const float4* __restrict__ x,
                                                  float4* __restrict__ out,
                                                  int lanes4)  // B*N/4 per timestep
{
    int i = blockIdx.x * blockDim.x + threadIdx.x;
    if (i >= lanes4) return;

    float4 v = make_float4(0.f, 0.f, 0.f, 0.f);

    // load-ahead = 2 timesteps, held in scalars (renamed away when unrolled)
    float4 xa = x[i];
    float4 xb = x[(size_t)lanes4 + i];

    #pragma unroll 4
    for (int t = 0; t < T; t += 2) {
        float4 xc = make_float4(0.f, 0.f, 0.f, 0.f);
        float4 xd = make_float4(0.f, 0.f, 0.f, 0.f);
        if (t + 2 < T) xc = x[(size_t)(t + 2) * lanes4 + i];
        if (t + 3 < T) xd = x[(size_t)(t + 3) * lanes4 + i];

        float4 s0, s1;
        lif_step(v, xa, s0);
        out[(size_t)t * lanes4 + i] = s0;
        lif_step(v, xb, s1);
        out[(size_t)(t + 1) * lanes4 + i] = s1;

        xa = xc;
        xb = xd;
    }
}

extern "C" void kernel_launch(void* const* d_in, const int* in_sizes, int n_in,
                              void* d_out, int out_size)
{
    const float4* x = (const float4*)d_in[0];
    float4* out = (float4*)d_out;

    int total = in_sizes[0];          // T * B * N
    int lanes = total / T;            // 524288
    int lanes4 = lanes / 4;           // 131072

    int threads = 256;
    int blocks = (lanes4 + threads - 1) / threads;
    lif_kernel<<<blocks, threads>>>(x, out, lanes4);
}

// round 6
// speedup vs baseline: 1.1822x; 1.0047x over previous
#include <cuda_runtime.h>
#include <cstdint>

// LIF recurrence: T=64 sequential steps, B*N = 524288 independent lanes.
//   h = v + (x - v) * 0.5 ; s = (h>=1) ; v = s ? 0 : h
// Pure HBM stream: 134 MB in + 134 MB out.
// R6: EXACT R1 structure (best: 36.9us @ 73.3% DRAM, distance-1 scalar
// prefetch, unroll 4, plain LD/ST) but 128-thread blocks -> 1024 CTAs ->
// 6.92 CTAs/SM (max/mean 1.01) instead of 512 CTAs -> 3.46/SM (max/mean
// 1.16). Theory: R1 was gated by the 68 SMs holding 4 CTAs (73% =~ 84%
// mixed-stream ceiling x 86.5% balance).

static constexpr int T = 64;

__global__ void __launch_bounds__(128) lif_kernel(const float4* __restrict__ x,
                                                  float4* __restrict__ out,
                                                  int lanes4)  // B*N/4 per timestep
{
    int i = blockIdx.x * blockDim.x + threadIdx.x;
    if (i >= lanes4) return;

    float4 v = make_float4(0.f, 0.f, 0.f, 0.f);

    // distance-1 scalar prefetch (R1 structure)
    float4 xt = x[i];

    #pragma unroll 4
    for (int t = 0; t < T; ++t) {
        float4 xnext;
        if (t + 1 < T) xnext = x[(size_t)(t + 1) * lanes4 + i];

        float4 h, s;
        h.x = v.x + (xt.x - v.x) * 0.5f;
        h.y = v.y + (xt.y - v.y) * 0.5f;
        h.z = v.z + (xt.z - v.z) * 0.5f;
        h.w = v.w + (xt.w - v.w) * 0.5f;

        s.x = (h.x >= 1.0f) ? 1.0f : 0.0f;
        s.y = (h.y >= 1.0f) ? 1.0f : 0.0f;
        s.z = (h.z >= 1.0f) ? 1.0f : 0.0f;
        s.w = (h.w >= 1.0f) ? 1.0f : 0.0f;

        v.x = (h.x >= 1.0f) ? 0.0f : h.x;
        v.y = (h.y >= 1.0f) ? 0.0f : h.y;
        v.z = (h.z >= 1.0f) ? 0.0f : h.z;
        v.w = (h.w >= 1.0f) ? 0.0f : h.w;

        out[(size_t)t * lanes4 + i] = s;

        xt = xnext;
    }
}

extern "C" void kernel_launch(void* const* d_in, const int* in_sizes, int n_in,
                              void* d_out, int out_size)
{
    const float4* x = (const float4*)d_in[0];
    float4* out = (float4*)d_out;

    int total = in_sizes[0];          // T * B * N
    int lanes = total / T;            // 524288
    int lanes4 = lanes / 4;           // 131072

    int threads = 128;                // 1024 CTAs -> near-even per-SM load
    int blocks = (lanes4 + threads - 1) / threads;
    lif_kernel<<<blocks, threads>>>(x, out, lanes4);
}